// round 1
// baseline (speedup 1.0000x reference)
#include <cuda_runtime.h>
#include <cuda_bf16.h>
#include <cstddef>

#define BATCH    256
#define DATA_DIM 8192
#define NNZ      256
#define QK       64
#define EMB      63
#define NSUB     8
#define K0S      260   // padded stride for transposed k0 in shared (multiple of 4, !mult of 32)

// Precomputed per-row projections of the embedding table (row 0 = padding row).
__device__ float g_Q0T[(DATA_DIM + 1) * QK];
__device__ float g_K0T[(DATA_DIM + 1) * QK];

// ---------------------------------------------------------------------------
// Kernel P: Q0T[p][d] = bq[d] + sum_e embed[p][e] * Wq[d][e+1]   (same for K)
// Grid: 129 blocks x 256 threads; each block covers 64 table rows.
// ---------------------------------------------------------------------------
__global__ void precompute_kernel(const float* __restrict__ embed,
                                  const float* __restrict__ Wq,
                                  const float* __restrict__ bq,
                                  const float* __restrict__ Wk,
                                  const float* __restrict__ bk) {
    __shared__ float WqT[64 * 65];
    __shared__ float WkT[64 * 65];
    __shared__ float bqs[64], bks[64];
    __shared__ float es[4][64];

    const int tid = threadIdx.x;
    for (int i = tid; i < 4096; i += 256) {
        int d = i >> 6, j = i & 63;
        WqT[j * 65 + d] = Wq[i];   // WqT[j][d] = Wq[d][j]
        WkT[j * 65 + d] = Wk[i];
    }
    if (tid < 64) { bqs[tid] = bq[tid]; bks[tid] = bk[tid]; }
    __syncthreads();

    const int d = tid & 63, r = tid >> 6;
    for (int it = 0; it < 16; ++it) {
        int p = blockIdx.x * 64 + it * 4 + r;
        if (d < EMB && p <= DATA_DIM) es[r][d] = embed[(size_t)p * EMB + d];
        __syncthreads();
        if (p <= DATA_DIM) {
            float q = bqs[d], k = bks[d];
#pragma unroll
            for (int e = 0; e < EMB; ++e) {
                float ev = es[r][e];
                q += ev * WqT[(e + 1) * 65 + d];
                k += ev * WkT[(e + 1) * 65 + d];
            }
            g_Q0T[(size_t)p * QK + d] = q;
            g_K0T[(size_t)p * QK + d] = k;
        }
        __syncthreads();
    }
}

// ---------------------------------------------------------------------------
// Kernel C: per-batch condense + RK4 integration + scatter of both planes.
// One block per batch, 256 threads (thread i owns position i).
// ---------------------------------------------------------------------------
struct SmemC {
    float k0[64 * K0S];   // transposed k0 [d][i]; ALSO reused as swizzled x staging
    float val[NNZ];
    int   idx[NNZ];
    float wsh[NNZ];
    float s[QK];
    float av[QK];
    float bv[QK];
    float mpart[256];
    float red1[8];
    float red2[8];
    int   wscan[8];
};

extern __shared__ unsigned char smem_raw[];

__global__ void __launch_bounds__(256, 2)
integrate_kernel(const float* __restrict__ t,
                 const float* __restrict__ x,
                 const float* __restrict__ Wq,
                 const float* __restrict__ Wk,
                 float* __restrict__ out) {
    SmemC* sm = reinterpret_cast<SmemC*>(smem_raw);
    const int tid  = threadIdx.x;
    const int b    = blockIdx.x;
    const int lane = tid & 31;
    const int wid  = tid >> 5;

    // ---- Phase 1: stage x row in shared (swizzled: elem i at i + i/32) ----
    float* xs = sm->k0;
    const float* xrow = x + (size_t)b * DATA_DIM;
    for (int i = tid; i < DATA_DIM; i += 256)
        xs[i + (i >> 5)] = xrow[i];
    if (tid < QK) { sm->av[tid] = Wq[tid * 64]; sm->bv[tid] = Wk[tid * 64]; }
    if (tid < NNZ) { sm->val[tid] = 0.0f; sm->idx[tid] = 0; }
    __syncthreads();

    // ---- Phase 2: order-preserving compaction (thread chunk [32t, 32t+32)) ----
    const int base = tid * 33;  // swizzled address of element tid*32
    int cnt = 0;
#pragma unroll
    for (int j = 0; j < 32; ++j) cnt += (xs[base + j] != 0.0f) ? 1 : 0;

    int inc = cnt;
#pragma unroll
    for (int o = 1; o < 32; o <<= 1) {
        int u = __shfl_up_sync(0xffffffffu, inc, o);
        if (lane >= o) inc += u;
    }
    if (lane == 31) sm->wscan[wid] = inc;
    __syncthreads();
    int woff = 0;
#pragma unroll
    for (int wdx = 0; wdx < 8; ++wdx) woff += (wdx < wid) ? sm->wscan[wdx] : 0;
    int o = woff + inc - cnt;  // exclusive prefix
#pragma unroll
    for (int j = 0; j < 32; ++j) {
        float v = xs[base + j];
        if (v != 0.0f && o < NNZ) {
            sm->val[o] = v;
            sm->idx[o] = tid * 32 + j;
            ++o;
        }
    }
    __syncthreads();

    // ---- Phase 3: gather q0 (registers) / k0 (shared, transposed) ----
    const int p     = sm->idx[tid] + 1;
    const float myv = sm->val[tid];

    // scatter initial plane (t=0)
    out[(size_t)b * DATA_DIM + (p - 1)] = myv;

    float q0r[QK];
    {
        const float4* qrow = reinterpret_cast<const float4*>(g_Q0T + (size_t)p * QK);
#pragma unroll
        for (int i = 0; i < 16; ++i) {
            float4 f = qrow[i];
            q0r[4 * i + 0] = f.x; q0r[4 * i + 1] = f.y;
            q0r[4 * i + 2] = f.z; q0r[4 * i + 3] = f.w;
        }
        const float4* krow = reinterpret_cast<const float4*>(g_K0T + (size_t)p * QK);
#pragma unroll
        for (int i = 0; i < 16; ++i) {
            float4 f = krow[i];
            int d = 4 * i;
            sm->k0[(d + 0) * K0S + tid] = f.x;
            sm->k0[(d + 1) * K0S + tid] = f.y;
            sm->k0[(d + 2) * K0S + tid] = f.z;
            sm->k0[(d + 3) * K0S + tid] = f.w;
        }
    }

    float vcur = myv;
    sm->wsh[tid] = vcur;
    const float dt = (t[1] - t[0]) * (1.0f / (float)NSUB);
    __syncthreads();

    const int dd = tid & 63, cc = tid >> 6;
    const float* krowsh = sm->k0 + dd * K0S + cc * 64;

    // dxdt(w) = w * (f - sum_j w_j f_j),  f_i = (w_i*(a.s) + q0_i.s) / 8,
    // s = (sum w^2)*b + K0^T w
    auto dxdt = [&](float w) -> float {
        // partial of m[d] over chunk cc (64 float4-vectorized MACs)
        float pm = 0.0f;
        const float4* wv4 = reinterpret_cast<const float4*>(sm->wsh + cc * 64);
        const float4* kv4 = reinterpret_cast<const float4*>(krowsh);
#pragma unroll
        for (int j = 0; j < 16; ++j) {
            float4 kv = kv4[j];
            float4 wv = wv4[j];
            pm += kv.x * wv.x; pm += kv.y * wv.y;
            pm += kv.z * wv.z; pm += kv.w * wv.w;
        }
        sm->mpart[tid] = pm;

        // S2 warp partials
        float w2 = w * w;
#pragma unroll
        for (int o2 = 16; o2 > 0; o2 >>= 1) w2 += __shfl_xor_sync(0xffffffffu, w2, o2);
        if (lane == 0) sm->red1[wid] = w2;
        __syncthreads();

        if (tid < QK) {
            float S2 = 0.0f;
#pragma unroll
            for (int k = 0; k < 8; ++k) S2 += sm->red1[k];
            float m = sm->mpart[tid] + sm->mpart[tid + 64] +
                      sm->mpart[tid + 128] + sm->mpart[tid + 192];
            sm->s[tid] = S2 * sm->bv[tid] + m;
        }
        __syncthreads();

        float qdot = 0.0f, c1 = 0.0f;
#pragma unroll
        for (int d = 0; d < QK; ++d) {
            float sv = sm->s[d];
            qdot += q0r[d] * sv;
            c1   += sm->av[d] * sv;
        }
        float f  = (c1 * w + qdot) * 0.125f;   // 1/sqrt(64)

        float wf = w * f;
#pragma unroll
        for (int o2 = 16; o2 > 0; o2 >>= 1) wf += __shfl_xor_sync(0xffffffffu, wf, o2);
        if (lane == 0) sm->red2[wid] = wf;
        __syncthreads();
        float g = 0.0f;
#pragma unroll
        for (int k = 0; k < 8; ++k) g += sm->red2[k];

        return w * (f - g);
    };

    // ---- Phase 4: 8 RK4 substeps over [t0, t1] ----
    for (int stp = 0; stp < NSUB; ++stp) {
        float k1 = dxdt(vcur);
        float w2s = vcur + 0.5f * dt * k1;
        sm->wsh[tid] = w2s; __syncthreads();
        float k2 = dxdt(w2s);
        float w3s = vcur + 0.5f * dt * k2;
        sm->wsh[tid] = w3s; __syncthreads();
        float k3 = dxdt(w3s);
        float w4s = vcur + dt * k3;
        sm->wsh[tid] = w4s; __syncthreads();
        float k4 = dxdt(w4s);
        vcur += dt * (1.0f / 6.0f) * (k1 + 2.0f * k2 + 2.0f * k3 + k4);
        sm->wsh[tid] = vcur; __syncthreads();
    }

    // scatter final plane (t=1)
    out[(size_t)BATCH * DATA_DIM + (size_t)b * DATA_DIM + (p - 1)] = vcur;
}

// ---------------------------------------------------------------------------
// kernel_launch
// ---------------------------------------------------------------------------
extern "C" void kernel_launch(void* const* d_in, const int* in_sizes, int n_in,
                              void* d_out, int out_size) {
    const float* t     = (const float*)d_in[0];
    const float* x     = (const float*)d_in[1];
    const float* embed = (const float*)d_in[2];
    const float* Wq    = (const float*)d_in[3];
    const float* bq    = (const float*)d_in[4];
    const float* Wk    = (const float*)d_in[5];
    const float* bk    = (const float*)d_in[6];
    float* out = (float*)d_out;

    // Opt-in to >48KB dynamic shared (executes immediately; not a stream op).
    cudaFuncSetAttribute(integrate_kernel,
                         cudaFuncAttributeMaxDynamicSharedMemorySize,
                         (int)sizeof(SmemC));

    // Zero the full output (poisoned to 0xAA by the harness).
    cudaMemsetAsync(d_out, 0, (size_t)out_size * sizeof(float), 0);

    precompute_kernel<<<(DATA_DIM + 1 + 63) / 64, 256>>>(embed, Wq, bq, Wk, bk);
    integrate_kernel<<<BATCH, 256, sizeof(SmemC)>>>(t, x, Wq, Wk, out);
}